// round 11
// baseline (speedup 1.0000x reference)
#include <cuda_runtime.h>
#include <cuda_fp16.h>

// Fixed problem shape: N=50000, E=1600000, D=U=128.
#define MAX_N 50048
#define D_DIM 128
#define BUCKET_CAP 128          // max degree; Binomial(1.6M,1/50K) max ~58, P(>=128)~0
#define BUCKET_SHIFT 7

// Packed fp32x2 FMA (Blackwell): one issue slot, two IEEE fp32 FMAs.
#define FMA_F32X2(d, a, b, c) \
    asm("fma.rn.f32x2 %0, %1, %2, %3;" : "=l"(d) : "l"(a), "l"(b), "l"(c))
#define PACK_F32X2(d, lo, hi) \
    asm("mov.b64 %0, {%1, %2};" : "=l"(d) : "f"(lo), "f"(hi))
#define UNPACK_F32X2(lo, hi, s) \
    asm("mov.b64 {%0, %1}, %2;" : "=f"(lo), "=f"(hi) : "l"(s))

// Scratch (__device__ globals; no allocations allowed).
__device__ int    g_counts[MAX_N];
__device__ int2   g_edges[(size_t)MAX_N * BUCKET_CAP];  // (dst, weight bits) buckets
__device__ __half g_featH[(size_t)MAX_N * D_DIM];       // fp16 copy of node_features

// ---------------------------------------------------------------------------
// fp32 -> fp16 feature table, fused with bucket-count zeroing (total4 > N).
__global__ void prep_kernel(const float* __restrict__ feat, int total4, int N) {
    int i = blockIdx.x * blockDim.x + threadIdx.x;
    if (i < total4) {
        float4 v = ((const float4*)feat)[i];
        __half2 h0 = __floats2half2_rn(v.x, v.y);
        __half2 h1 = __floats2half2_rn(v.z, v.w);
        uint2 u;
        *reinterpret_cast<__half2*>(&u.x) = h0;
        *reinterpret_cast<__half2*>(&u.y) = h1;
        ((uint2*)g_featH)[i] = u;
    }
    if (i < N) g_counts[i] = 0;
}

// Single-pass edge bucketing: the histogram atomic IS the scatter cursor.
// Replaces hist + 3 scan kernels + scatter. 4 edges/thread for ILP.
__global__ void bucket_kernel(const int* __restrict__ src,
                              const int* __restrict__ dst,
                              const float* __restrict__ w, int E) {
    int i = (blockIdx.x * blockDim.x + threadIdx.x) * 4;
    if (i + 4 <= E) {
        int4   s  = *(const int4*)(src + i);
        int4   d  = *(const int4*)(dst + i);
        float4 ww = *(const float4*)(w + i);
        int p0 = atomicAdd(&g_counts[s.x], 1);
        int p1 = atomicAdd(&g_counts[s.y], 1);
        int p2 = atomicAdd(&g_counts[s.z], 1);
        int p3 = atomicAdd(&g_counts[s.w], 1);
        g_edges[((size_t)s.x << BUCKET_SHIFT) + p0] = make_int2(d.x, __float_as_int(ww.x));
        g_edges[((size_t)s.y << BUCKET_SHIFT) + p1] = make_int2(d.y, __float_as_int(ww.y));
        g_edges[((size_t)s.z << BUCKET_SHIFT) + p2] = make_int2(d.z, __float_as_int(ww.z));
        g_edges[((size_t)s.w << BUCKET_SHIFT) + p3] = make_int2(d.w, __float_as_int(ww.w));
    } else {
        for (int j = i; j < E; j++) {
            int sj = src[j];
            int p = atomicAdd(&g_counts[sj], 1);
            g_edges[((size_t)sj << BUCKET_SHIFT) + p] =
                make_int2(dst[j], __float_as_int(w[j]));
        }
    }
}

// ---------------------------------------------------------------------------
// Fused aggregate (fp16 gather, depth-2 pipelined) + GEMM (FFMA2) + bias + relu.
#define ROWS_PER_WARP 4
#define FWARPS 8
#define FTILE (FWARPS * ROWS_PER_WARP)  // 32 nodes per block-tile

__global__ __launch_bounds__(256, 2)
void fused_agg_gemm_kernel(const float* __restrict__ W,
                           const float* __restrict__ b,
                           float* __restrict__ out, int N) {
    extern __shared__ float sh[];
    float* Ws   = sh;                            // [128][128]
    float* bs   = Ws + D_DIM * D_DIM;            // [128]
    float* aggs = bs + D_DIM;                    // [8][4][128]

    const int tid = threadIdx.x;
    const float4* Wv = (const float4*)W;
    float4* Wsv = (float4*)Ws;
#pragma unroll
    for (int i = 0; i < 16; i++) Wsv[tid + i * 256] = Wv[tid + i * 256];
    if (tid < D_DIM) bs[tid] = b[tid];
    __syncthreads();

    const int warp = tid >> 5, lane = tid & 31;
    float* myagg = aggs + warp * ROWS_PER_WARP * D_DIM;
    const uint2* fH = (const uint2*)g_featH;

    const int tiles = (N + FTILE - 1) / FTILE;
    for (int t = blockIdx.x; t < tiles; t += gridDim.x) {
        const int base = t * FTILE + warp * ROWS_PER_WARP;

        // ---- gather phase: weighted mean per node row, depth-2 pipeline ----
#pragma unroll
        for (int r = 0; r < ROWS_PER_WARP; r++) {
            int node = base + r;
            unsigned long long sAB = 0ull, sCD = 0ull;   // packed (x,y),(z,w)
            float den = 0.f;
            if (node < N) {
                const int beg = node << BUCKET_SHIFT;
                const int end = beg + g_counts[node];
                const int nch = (end - beg + 3) >> 2;    // masked 4-edge chunks
                if (nch > 0) {
#define LDE(a0, a1, a2, a3, jj) do {                                          \
    a0 = ((jj) + 0 < end) ? g_edges[(jj) + 0] : make_int2(0, 0);              \
    a1 = ((jj) + 1 < end) ? g_edges[(jj) + 1] : make_int2(0, 0);              \
    a2 = ((jj) + 2 < end) ? g_edges[(jj) + 2] : make_int2(0, 0);              \
    a3 = ((jj) + 3 < end) ? g_edges[(jj) + 3] : make_int2(0, 0);              \
} while (0)
#define LDH(x0, x1, x2, x3, a0, a1, a2, a3) do {                              \
    x0 = fH[(size_t)(a0).x * 32 + lane];                                      \
    x1 = fH[(size_t)(a1).x * 32 + lane];                                      \
    x2 = fH[(size_t)(a2).x * 32 + lane];                                      \
    x3 = fH[(size_t)(a3).x * 32 + lane];                                      \
} while (0)
#define EDGE_ACC(hh, wsc) do {                                                \
    float2 p_ = __half22float2(*reinterpret_cast<__half2*>(&(hh).x));         \
    float2 q_ = __half22float2(*reinterpret_cast<__half2*>(&(hh).y));         \
    unsigned long long pp_, qq_, ww_;                                         \
    PACK_F32X2(pp_, p_.x, p_.y);                                              \
    PACK_F32X2(qq_, q_.x, q_.y);                                              \
    PACK_F32X2(ww_, (wsc), (wsc));                                            \
    FMA_F32X2(sAB, ww_, pp_, sAB);                                            \
    FMA_F32X2(sCD, ww_, qq_, sCD);                                            \
} while (0)
#define ACC4() do {                                                           \
    float w0_ = __int_as_float(e0.y), w1_ = __int_as_float(e1.y);             \
    float w2_ = __int_as_float(e2.y), w3_ = __int_as_float(e3.y);             \
    EDGE_ACC(h0, w0_); EDGE_ACC(h1, w1_);                                     \
    EDGE_ACC(h2, w2_); EDGE_ACC(h3, w3_);                                     \
    den += (w0_ + w1_) + (w2_ + w3_);                                         \
} while (0)
                    int2 e0, e1, e2, e3;      // edges: chunk c (being accumulated)
                    int2 f0, f1, f2, f3;      // edges: chunk c+1 (features pending)
                    uint2 h0, h1, h2, h3;     // features: chunk c
                    int j = beg;
                    LDE(e0, e1, e2, e3, j);               // chunk 0 edges
                    LDH(h0, h1, h2, h3, e0, e1, e2, e3);  // chunk 0 features
                    j += 4;
                    if (nch > 1) LDE(f0, f1, f2, f3, j);  // chunk 1 edges
                    for (int c = 0; c + 2 < nch; c++) {
                        j += 4;
                        int2 g0, g1, g2, g3;
                        LDE(g0, g1, g2, g3, j);           // chunk c+2 edges
                        uint2 n0, n1, n2, n3;
                        LDH(n0, n1, n2, n3, f0, f1, f2, f3);  // chunk c+1 feats
                        ACC4();                            // accumulate chunk c
                        e0 = f0; e1 = f1; e2 = f2; e3 = f3;
                        f0 = g0; f1 = g1; f2 = g2; f3 = g3;
                        h0 = n0; h1 = n1; h2 = n2; h3 = n3;
                    }
                    if (nch > 1) {
                        uint2 n0, n1, n2, n3;
                        LDH(n0, n1, n2, n3, f0, f1, f2, f3);  // last chunk feats
                        ACC4();                                // chunk nch-2
                        e0 = f0; e1 = f1; e2 = f2; e3 = f3;
                        h0 = n0; h1 = n1; h2 = n2; h3 = n3;
                    }
                    ACC4();                                    // last chunk
#undef ACC4
#undef EDGE_ACC
#undef LDH
#undef LDE
                }
            }
            float ax, ay, az, aw;
            UNPACK_F32X2(ax, ay, sAB);
            UNPACK_F32X2(az, aw, sCD);
            float inv = 1.0f / fmaxf(den, 1e-12f);
            *(float4*)(myagg + r * D_DIM + lane * 4) =
                make_float4(ax * inv, ay * inv, az * inv, aw * inv);
        }
        __syncwarp();

        // ---- GEMM phase: packed FFMA2, 4 rows x 4 cols per thread ----
        unsigned long long accA[ROWS_PER_WARP], accB[ROWS_PER_WARP];
#pragma unroll
        for (int r = 0; r < ROWS_PER_WARP; r++) { accA[r] = 0ull; accB[r] = 0ull; }

#pragma unroll 8
        for (int k = 0; k < D_DIM; k += 4) {
            float4 a[ROWS_PER_WARP];
#pragma unroll
            for (int r = 0; r < ROWS_PER_WARP; r++)
                a[r] = *(float4*)(myagg + r * D_DIM + k);
#pragma unroll
            for (int kk = 0; kk < 4; kk++) {
                ulonglong2 wp = *(ulonglong2*)(Ws + (k + kk) * D_DIM + lane * 4);
#pragma unroll
                for (int r = 0; r < ROWS_PER_WARP; r++) {
                    float av = ((float*)&a[r])[kk];
                    unsigned long long avv;
                    PACK_F32X2(avv, av, av);
                    FMA_F32X2(accA[r], avv, wp.x, accA[r]);
                    FMA_F32X2(accB[r], avv, wp.y, accB[r]);
                }
            }
        }

        float4 bb = *(float4*)(bs + lane * 4);
#pragma unroll
        for (int r = 0; r < ROWS_PER_WARP; r++) {
            int row = base + r;
            if (row < N) {
                float ox, oy, oz, ow;
                UNPACK_F32X2(ox, oy, accA[r]);
                UNPACK_F32X2(oz, ow, accB[r]);
                float4 o;
                o.x = fmaxf(ox + bb.x, 0.f);
                o.y = fmaxf(oy + bb.y, 0.f);
                o.z = fmaxf(oz + bb.z, 0.f);
                o.w = fmaxf(ow + bb.w, 0.f);
                *(float4*)(out + (size_t)row * D_DIM + lane * 4) = o;
            }
        }
        __syncwarp();
    }
}

// ---------------------------------------------------------------------------
extern "C" void kernel_launch(void* const* d_in, const int* in_sizes, int n_in,
                              void* d_out, int out_size) {
    const float* feat = (const float*)d_in[0];   // [N,128]
    const int*   src  = (const int*)d_in[1];     // [E]
    const int*   dst  = (const int*)d_in[2];     // [E]
    const float* w    = (const float*)d_in[3];   // [E]
    const float* W    = (const float*)d_in[4];   // [128,128]
    const float* b    = (const float*)d_in[5];   // [128]
    float* out = (float*)d_out;

    const int N = in_sizes[0] / D_DIM;
    const int E = in_sizes[1];

    {
        int total4 = N * (D_DIM / 4);
        prep_kernel<<<(total4 + 255) / 256, 256>>>(feat, total4, N);
    }
    bucket_kernel<<<((E + 3) / 4 + 255) / 256, 256>>>(src, dst, w, E);

    const int smem = (D_DIM * D_DIM + D_DIM +
                      FWARPS * ROWS_PER_WARP * D_DIM) * (int)sizeof(float);  // 82432 B
    cudaFuncSetAttribute(fused_agg_gemm_kernel,
                         cudaFuncAttributeMaxDynamicSharedMemorySize, smem);
    fused_agg_gemm_kernel<<<296, 256, smem>>>(W, b, out, N);
}

// round 12
// speedup vs baseline: 1.2123x; 1.2123x over previous
#include <cuda_runtime.h>
#include <cuda_fp16.h>

// Fixed problem shape: N=50000, E=1600000, D=U=128.
#define MAX_N 50048
#define MAX_E 1600000
#define D_DIM 128

#define SCAN_BLK   256
#define SCAN_ITEMS 16
#define SCAN_TILE  (SCAN_BLK * SCAN_ITEMS)   // 4096
#define MAX_SCAN_BLKS 16

// Packed fp32x2 FMA (Blackwell): one issue slot, two IEEE fp32 FMAs.
#define FMA_F32X2(d, a, b, c) \
    asm("fma.rn.f32x2 %0, %1, %2, %3;" : "=l"(d) : "l"(a), "l"(b), "l"(c))
#define PACK_F32X2(d, lo, hi) \
    asm("mov.b64 %0, {%1, %2};" : "=l"(d) : "f"(lo), "f"(hi))
#define UNPACK_F32X2(lo, hi, s) \
    asm("mov.b64 {%0, %1}, %2;" : "=f"(lo), "=f"(hi) : "l"(s))

// Scratch (__device__ globals; no allocations allowed).
__device__ int    g_counts[MAX_N];
__device__ int    g_offsets[MAX_N + 1];
__device__ int    g_cursor[MAX_N];
__device__ int    g_blocksum[MAX_SCAN_BLKS];   // inclusive per-block sums
__device__ int    g_flags[MAX_SCAN_BLKS];      // lookback ready flags
__device__ int2   g_edges[MAX_E];              // (dst, weight bits), CSR by src
__device__ __half g_featH[(size_t)MAX_N * D_DIM];

// ---------------------------------------------------------------------------
// fp32 -> fp16 feature table, fused with zeroing counts + scan flags.
__global__ void prep_kernel(const float* __restrict__ feat, int total4, int N) {
    int i = blockIdx.x * blockDim.x + threadIdx.x;
    if (i < total4) {
        float4 v = ((const float4*)feat)[i];
        __half2 h0 = __floats2half2_rn(v.x, v.y);
        __half2 h1 = __floats2half2_rn(v.z, v.w);
        uint2 u;
        *reinterpret_cast<__half2*>(&u.x) = h0;
        *reinterpret_cast<__half2*>(&u.y) = h1;
        ((uint2*)g_featH)[i] = u;
    }
    if (i < N) g_counts[i] = 0;
    if (i < MAX_SCAN_BLKS) { g_flags[i] = 0; g_blocksum[i] = 0; }
}

// histogram of edge_src, 4 edges/thread
__global__ void hist_kernel(const int* __restrict__ src, int E) {
    int i = (blockIdx.x * blockDim.x + threadIdx.x) * 4;
    if (i + 4 <= E) {
        int4 s = *(const int4*)(src + i);
        atomicAdd(&g_counts[s.x], 1);
        atomicAdd(&g_counts[s.y], 1);
        atomicAdd(&g_counts[s.z], 1);
        atomicAdd(&g_counts[s.w], 1);
    } else {
        for (int j = i; j < E; j++) atomicAdd(&g_counts[src[j]], 1);
    }
}

// ---- single-pass exclusive scan (decoupled lookback; nblk=13 <= #SMs) ----
__global__ void scan_kernel(int N, int nblk) {
    __shared__ int swarp[SCAN_BLK / 32];
    __shared__ int s_prev;
    const int tid = threadIdx.x, lane = tid & 31, wid = tid >> 5;
    const int b = blockIdx.x;
    int start = b * SCAN_TILE + tid * SCAN_ITEMS;

    int vals[SCAN_ITEMS];
    int local = 0;
    if (start + SCAN_ITEMS <= N) {
#pragma unroll
        for (int v = 0; v < SCAN_ITEMS / 4; v++) {
            int4 c = *(const int4*)(g_counts + start + v * 4);
            vals[v * 4 + 0] = c.x; vals[v * 4 + 1] = c.y;
            vals[v * 4 + 2] = c.z; vals[v * 4 + 3] = c.w;
            local += c.x + c.y + c.z + c.w;
        }
    } else {
#pragma unroll
        for (int i = 0; i < SCAN_ITEMS; i++) {
            int idx = start + i;
            vals[i] = (idx < N) ? g_counts[idx] : 0;
            local += vals[i];
        }
    }
    // block-internal inclusive scan of per-thread sums
    int x = local;
#pragma unroll
    for (int off = 1; off < 32; off <<= 1) {
        int y = __shfl_up_sync(0xffffffffu, x, off);
        if (lane >= off) x += y;
    }
    if (lane == 31) swarp[wid] = x;
    __syncthreads();
    if (wid == 0 && lane < SCAN_BLK / 32) {
        int v = swarp[lane];
        int xv = v;
#pragma unroll
        for (int off = 1; off < SCAN_BLK / 32; off <<= 1) {
            int y = __shfl_up_sync(0xffu, xv, off);
            if (lane >= off) xv += y;
        }
        swarp[lane] = xv - v;   // exclusive warp prefix
    }
    __syncthreads();
    int within = swarp[wid] + (x - local);       // exclusive prefix within block
    int blktot = 0;
    if (tid == SCAN_BLK - 1) blktot = within + local;  // block total (last thread)

    // lookback: thread (SCAN_BLK-1) publishes inclusive sum; waits for b-1.
    if (tid == SCAN_BLK - 1) {
        int prev = 0;
        if (b > 0) {
            while (atomicAdd(&g_flags[b - 1], 0) == 0) { }
            prev = g_blocksum[b - 1];
        }
        g_blocksum[b] = prev + blktot;
        __threadfence();
        atomicExch(&g_flags[b], 1);
        s_prev = prev;
        if (b == nblk - 1) g_offsets[N] = prev + blktot;
    }
    __syncthreads();
    int pre = s_prev + within;
    if (start + SCAN_ITEMS <= N) {
#pragma unroll
        for (int i = 0; i < SCAN_ITEMS; i++) {
            g_offsets[start + i] = pre;
            g_cursor[start + i] = pre;
            pre += vals[i];
        }
    } else {
        for (int i = 0; i < SCAN_ITEMS; i++) {
            int idx = start + i;
            if (idx < N) { g_offsets[idx] = pre; g_cursor[idx] = pre; }
            pre += vals[i];
        }
    }
}

// scatter edges into CSR order, 4 edges/thread for atomic/store ILP
__global__ void scatter_kernel(const int* __restrict__ src,
                               const int* __restrict__ dst,
                               const float* __restrict__ w, int E) {
    int i = (blockIdx.x * blockDim.x + threadIdx.x) * 4;
    if (i + 4 <= E) {
        int4   s  = *(const int4*)(src + i);
        int4   d  = *(const int4*)(dst + i);
        float4 ww = *(const float4*)(w + i);
        int p0 = atomicAdd(&g_cursor[s.x], 1);
        int p1 = atomicAdd(&g_cursor[s.y], 1);
        int p2 = atomicAdd(&g_cursor[s.z], 1);
        int p3 = atomicAdd(&g_cursor[s.w], 1);
        g_edges[p0] = make_int2(d.x, __float_as_int(ww.x));
        g_edges[p1] = make_int2(d.y, __float_as_int(ww.y));
        g_edges[p2] = make_int2(d.z, __float_as_int(ww.z));
        g_edges[p3] = make_int2(d.w, __float_as_int(ww.w));
    } else {
        for (int j = i; j < E; j++) {
            int p = atomicAdd(&g_cursor[src[j]], 1);
            g_edges[p] = make_int2(dst[j], __float_as_int(w[j]));
        }
    }
}

// ---------------------------------------------------------------------------
// Fused aggregate (fp16 gather, depth-2 pipelined) + GEMM (FFMA2) + bias + relu.
// 512 threads (16 warps) share ONE smem W tile -> 32 warps/SM at 2 blocks/SM.
#define ROWS_PER_WARP 4
#define FWARPS 16
#define FTHREADS (FWARPS * 32)          // 512
#define FTILE (FWARPS * ROWS_PER_WARP)  // 64 nodes per block-tile

__global__ __launch_bounds__(FTHREADS, 2)
void fused_agg_gemm_kernel(const float* __restrict__ W,
                           const float* __restrict__ b,
                           float* __restrict__ out, int N) {
    extern __shared__ float sh[];
    float* Ws   = sh;                            // [128][128]
    float* bs   = Ws + D_DIM * D_DIM;            // [128]
    float* aggs = bs + D_DIM;                    // [16][4][128]

    const int tid = threadIdx.x;
    // cooperative W load: 16384 floats / 512 threads = 8 float4 each
    const float4* Wv = (const float4*)W;
    float4* Wsv = (float4*)Ws;
#pragma unroll
    for (int i = 0; i < 8; i++) Wsv[tid + i * FTHREADS] = Wv[tid + i * FTHREADS];
    if (tid < D_DIM) bs[tid] = b[tid];
    __syncthreads();

    const int warp = tid >> 5, lane = tid & 31;
    float* myagg = aggs + warp * ROWS_PER_WARP * D_DIM;
    const uint2* fH = (const uint2*)g_featH;

    const int tiles = (N + FTILE - 1) / FTILE;
    for (int t = blockIdx.x; t < tiles; t += gridDim.x) {
        const int base = t * FTILE + warp * ROWS_PER_WARP;

        // ---- gather phase: weighted mean per node row, depth-2 pipeline ----
#pragma unroll
        for (int r = 0; r < ROWS_PER_WARP; r++) {
            int node = base + r;
            unsigned long long sAB = 0ull, sCD = 0ull;   // packed (x,y),(z,w)
            float den = 0.f;
            if (node < N) {
                const int beg = g_offsets[node], end = g_offsets[node + 1];
                const int nch = (end - beg + 3) >> 2;    // masked 4-edge chunks
                if (nch > 0) {
#define LDE(a0, a1, a2, a3, jj) do {                                          \
    a0 = ((jj) + 0 < end) ? g_edges[(jj) + 0] : make_int2(0, 0);              \
    a1 = ((jj) + 1 < end) ? g_edges[(jj) + 1] : make_int2(0, 0);              \
    a2 = ((jj) + 2 < end) ? g_edges[(jj) + 2] : make_int2(0, 0);              \
    a3 = ((jj) + 3 < end) ? g_edges[(jj) + 3] : make_int2(0, 0);              \
} while (0)
#define LDH(x0, x1, x2, x3, a0, a1, a2, a3) do {                              \
    x0 = fH[(size_t)(a0).x * 32 + lane];                                      \
    x1 = fH[(size_t)(a1).x * 32 + lane];                                      \
    x2 = fH[(size_t)(a2).x * 32 + lane];                                      \
    x3 = fH[(size_t)(a3).x * 32 + lane];                                      \
} while (0)
#define EDGE_ACC(hh, wsc) do {                                                \
    float2 p_ = __half22float2(*reinterpret_cast<__half2*>(&(hh).x));         \
    float2 q_ = __half22float2(*reinterpret_cast<__half2*>(&(hh).y));         \
    unsigned long long pp_, qq_, ww_;                                         \
    PACK_F32X2(pp_, p_.x, p_.y);                                              \
    PACK_F32X2(qq_, q_.x, q_.y);                                              \
    PACK_F32X2(ww_, (wsc), (wsc));                                            \
    FMA_F32X2(sAB, ww_, pp_, sAB);                                            \
    FMA_F32X2(sCD, ww_, qq_, sCD);                                            \
} while (0)
#define ACC4() do {                                                           \
    float w0_ = __int_as_float(e0.y), w1_ = __int_as_float(e1.y);             \
    float w2_ = __int_as_float(e2.y), w3_ = __int_as_float(e3.y);             \
    EDGE_ACC(h0, w0_); EDGE_ACC(h1, w1_);                                     \
    EDGE_ACC(h2, w2_); EDGE_ACC(h3, w3_);                                     \
    den += (w0_ + w1_) + (w2_ + w3_);                                         \
} while (0)
                    int2 e0, e1, e2, e3;      // edges: chunk c (being accumulated)
                    int2 f0, f1, f2, f3;      // edges: chunk c+1 (features pending)
                    uint2 h0, h1, h2, h3;     // features: chunk c
                    int j = beg;
                    LDE(e0, e1, e2, e3, j);               // chunk 0 edges
                    LDH(h0, h1, h2, h3, e0, e1, e2, e3);  // chunk 0 features
                    j += 4;
                    if (nch > 1) LDE(f0, f1, f2, f3, j);  // chunk 1 edges
                    for (int c = 0; c + 2 < nch; c++) {
                        j += 4;
                        int2 g0, g1, g2, g3;
                        LDE(g0, g1, g2, g3, j);           // chunk c+2 edges
                        uint2 n0, n1, n2, n3;
                        LDH(n0, n1, n2, n3, f0, f1, f2, f3);  // chunk c+1 feats
                        ACC4();                            // accumulate chunk c
                        e0 = f0; e1 = f1; e2 = f2; e3 = f3;
                        f0 = g0; f1 = g1; f2 = g2; f3 = g3;
                        h0 = n0; h1 = n1; h2 = n2; h3 = n3;
                    }
                    if (nch > 1) {
                        uint2 n0, n1, n2, n3;
                        LDH(n0, n1, n2, n3, f0, f1, f2, f3);  // last chunk feats
                        ACC4();                                // chunk nch-2
                        e0 = f0; e1 = f1; e2 = f2; e3 = f3;
                        h0 = n0; h1 = n1; h2 = n2; h3 = n3;
                    }
                    ACC4();                                    // last chunk
#undef ACC4
#undef EDGE_ACC
#undef LDH
#undef LDE
                }
            }
            float ax, ay, az, aw;
            UNPACK_F32X2(ax, ay, sAB);
            UNPACK_F32X2(az, aw, sCD);
            float inv = 1.0f / fmaxf(den, 1e-12f);
            *(float4*)(myagg + r * D_DIM + lane * 4) =
                make_float4(ax * inv, ay * inv, az * inv, aw * inv);
        }
        __syncwarp();

        // ---- GEMM phase: packed FFMA2, 4 rows x 4 cols per thread ----
        unsigned long long accA[ROWS_PER_WARP], accB[ROWS_PER_WARP];
#pragma unroll
        for (int r = 0; r < ROWS_PER_WARP; r++) { accA[r] = 0ull; accB[r] = 0ull; }

#pragma unroll 8
        for (int k = 0; k < D_DIM; k += 4) {
            float4 a[ROWS_PER_WARP];
#pragma unroll
            for (int r = 0; r < ROWS_PER_WARP; r++)
                a[r] = *(float4*)(myagg + r * D_DIM + k);
#pragma unroll
            for (int kk = 0; kk < 4; kk++) {
                ulonglong2 wp = *(ulonglong2*)(Ws + (k + kk) * D_DIM + lane * 4);
#pragma unroll
                for (int r = 0; r < ROWS_PER_WARP; r++) {
                    float av = ((float*)&a[r])[kk];
                    unsigned long long avv;
                    PACK_F32X2(avv, av, av);
                    FMA_F32X2(accA[r], avv, wp.x, accA[r]);
                    FMA_F32X2(accB[r], avv, wp.y, accB[r]);
                }
            }
        }

        float4 bb = *(float4*)(bs + lane * 4);
#pragma unroll
        for (int r = 0; r < ROWS_PER_WARP; r++) {
            int row = base + r;
            if (row < N) {
                float ox, oy, oz, ow;
                UNPACK_F32X2(ox, oy, accA[r]);
                UNPACK_F32X2(oz, ow, accB[r]);
                float4 o;
                o.x = fmaxf(ox + bb.x, 0.f);
                o.y = fmaxf(oy + bb.y, 0.f);
                o.z = fmaxf(oz + bb.z, 0.f);
                o.w = fmaxf(ow + bb.w, 0.f);
                *(float4*)(out + (size_t)row * D_DIM + lane * 4) = o;
            }
        }
        __syncwarp();
    }
}

// ---------------------------------------------------------------------------
extern "C" void kernel_launch(void* const* d_in, const int* in_sizes, int n_in,
                              void* d_out, int out_size) {
    const float* feat = (const float*)d_in[0];   // [N,128]
    const int*   src  = (const int*)d_in[1];     // [E]
    const int*   dst  = (const int*)d_in[2];     // [E]
    const float* w    = (const float*)d_in[3];   // [E]
    const float* W    = (const float*)d_in[4];   // [128,128]
    const float* b    = (const float*)d_in[5];   // [128]
    float* out = (float*)d_out;

    const int N = in_sizes[0] / D_DIM;
    const int E = in_sizes[1];

    {
        int total4 = N * (D_DIM / 4);
        prep_kernel<<<(total4 + 255) / 256, 256>>>(feat, total4, N);
    }
    hist_kernel<<<((E + 3) / 4 + 255) / 256, 256>>>(src, E);

    const int nblk = (N + SCAN_TILE - 1) / SCAN_TILE;   // 13 (<= #SMs: safe lookback)
    scan_kernel<<<nblk, SCAN_BLK>>>(N, nblk);

    scatter_kernel<<<((E + 3) / 4 + 255) / 256, 256>>>(src, dst, w, E);

    const int smem = (D_DIM * D_DIM + D_DIM +
                      FWARPS * ROWS_PER_WARP * D_DIM) * (int)sizeof(float);  // 98816 B
    cudaFuncSetAttribute(fused_agg_gemm_kernel,
                         cudaFuncAttributeMaxDynamicSharedMemorySize, smem);
    fused_agg_gemm_kernel<<<296, FTHREADS, smem>>>(W, b, out, N);
}